// round 17
// baseline (speedup 1.0000x reference)
#include <cuda_runtime.h>
#define NSTEP 255

__device__ float g_Wbig[8 * 128 * 256];
__device__ float g_cond[NSTEP * 2 * 1024];
__device__ float g_ds1[2 * 64 * 512];
__device__ float g_ds2[2 * 64 * 256];
__device__ float g_outpre[2 * 64 * 256];
__device__ float g_up1[2 * 64 * 512];

__device__ __forceinline__ float dot4(float4 a, float4 x) {
    return a.x * x.x + a.y * x.y + a.z * x.z + a.w * x.w;
}
__device__ __forceinline__ float gatefn(float z0, float z1) {
    float e0 = __expf(2.f * z0), e1 = __expf(-z1);
    return (1.f - __fdividef(2.f, e0 + 1.f)) * __fdividef(1.f, 1.f + e1);
}

__global__ void k_downbn(int sel, const float* __restrict__ w,
                         const float* __restrict__ song,
                         const float* __restrict__ gamma,
                         const float* __restrict__ beta) {
    int o = blockIdx.x, tid = threadIdx.x;
    int Lout = sel ? 256 : 512;
    const float* in = sel ? g_ds1 : song;
    float* out = sel ? g_ds2 : g_ds1;
    __shared__ float wr[128], rs[256], rq[256];
    if (tid < 128) wr[tid] = w[o * 128 + tid];
    __syncthreads();
    float vals[4];
    int cnt = 2 * Lout / 256;
    float s = 0.f, q = 0.f;
    for (int j = 0; j < cnt; j++) {
        int i = tid + j * 256, bb = i >= Lout, l = i - bb * Lout;
        const float* xin = in + bb * 64 * 2 * Lout;
        float acc = 0.f;
#pragma unroll
        for (int c = 0; c < 64; c++)
            acc += wr[2 * c] * xin[c * 2 * Lout + 2 * l]
                 + wr[2 * c + 1] * xin[c * 2 * Lout + 2 * l + 1];
        vals[j] = acc; s += acc; q += acc * acc;
    }
    rs[tid] = s; rq[tid] = q; __syncthreads();
    for (int st = 128; st; st >>= 1) {
        if (tid < st) { rs[tid] += rs[tid + st]; rq[tid] += rq[tid + st]; }
        __syncthreads();
    }
    float m = rs[0] / (2.f * Lout);
    float inv = rsqrtf(rq[0] / (2.f * Lout) - m * m + 1e-5f);
    float ga = gamma[o], be = beta[o];
    for (int j = 0; j < cnt; j++) {
        int i = tid + j * 256, bb = i >= Lout, l = i - bb * Lout;
        out[(bb * 64 + o) * Lout + l] = fmaxf(ga * (vals[j] - m) * inv + be, 0.f);
    }
}

__global__ void k_upbn(int sel, const float* __restrict__ w,
                       const float* __restrict__ gamma,
                       const float* __restrict__ beta, float* __restrict__ hout) {
    int o = blockIdx.x, tid = threadIdx.x;
    int Lin = sel ? 512 : 256;
    const float* in = sel ? g_up1 : g_outpre;
    float* out = sel ? hout : g_up1;
    __shared__ float wr[128], rs[256], rq[256];
    if (tid < 128) { int i = tid >> 1, k = tid & 1; wr[tid] = w[(i * 64 + o) * 2 + k]; }
    __syncthreads();
    int cnt = 2 * Lin / 256;
    float v0[4], v1[4];
    float s = 0.f, q = 0.f;
    for (int j = 0; j < cnt; j++) {
        int i = tid + j * 256, bb = i >= Lin, l = i - bb * Lin;
        float a0 = 0.f, a1 = 0.f;
#pragma unroll
        for (int c = 0; c < 64; c++) {
            float x = in[(bb * 64 + c) * Lin + l];
            a0 += wr[2 * c] * x; a1 += wr[2 * c + 1] * x;
        }
        v0[j] = a0; v1[j] = a1;
        s += a0 + a1; q += a0 * a0 + a1 * a1;
    }
    rs[tid] = s; rq[tid] = q; __syncthreads();
    for (int st = 128; st; st >>= 1) {
        if (tid < st) { rs[tid] += rs[tid + st]; rq[tid] += rq[tid + st]; }
        __syncthreads();
    }
    float m = rs[0] / (4.f * Lin);
    float inv = rsqrtf(rq[0] / (4.f * Lin) - m * m + 1e-5f);
    float ga = gamma[o], be = beta[o];
    for (int j = 0; j < cnt; j++) {
        int i = tid + j * 256, bb = i >= Lin, l = i - bb * Lin;
        float* op = out + (bb * 64 + o) * 2 * Lin + 2 * l;
        op[0] = fmaxf(ga * (v0[j] - m) * inv + be, 0.f);
        op[1] = fmaxf(ga * (v1[j] - m) * inv + be, 0.f);
    }
}

// prep: cond (0-127), Wbig pack (128-1151), zero (1152)
// g_Wbig[l][row][0:64)=Wzo_l  [64:128)=F_l=Wzc_l*Wembed
//            [128:192)=Wzc_l (0 for l<2)  [192:256)=M_l=Wzc_l*Wres_{l-1} (0 for l=0)
__global__ void k_prep(const float* __restrict__ wdil,
                       const float* __restrict__ wcond,
                       const float* __restrict__ wres,
                       const float* __restrict__ wembed) {
    int bx = blockIdx.x, tid = threadIdx.x;
    if (bx >= 1152) {
        if (tid < 128) g_outpre[tid * 256] = 0.f;
        return;
    }
    if (bx >= 128) {
        int idx = (bx - 128) * 256 + tid;
        int l = idx >> 15, rem = idx & 32767;
        int row = rem >> 8, c = rem & 255;
        float val;
        if (c < 64) {
            val = wdil[((l * 128 + row) * 64 + c) * 2];
        } else if (c < 128) {
            int k = c - 64;
            float acc = 0.f;
            for (int r = 0; r < 64; r++)
                acc += wdil[((l * 128 + row) * 64 + r) * 2 + 1] * wembed[r * 64 + k];
            val = acc;
        } else if (c < 192) {
            int k = c - 128;
            val = (l < 2) ? 0.f : wdil[((l * 128 + row) * 64 + k) * 2 + 1];
        } else {
            int k = c - 192;
            if (l == 0) val = 0.f;
            else {
                float acc = 0.f;
                for (int r = 0; r < 64; r++)
                    acc += wdil[((l * 128 + row) * 64 + r) * 2 + 1]
                         * wres[((l - 1) * 64 + r) * 64 + k];
                val = acc;
            }
        }
        g_Wbig[idx] = val;
        return;
    }
    __shared__ __align__(16) float wt[128 * 64];
    __shared__ __align__(16) float col[128];
    int ob = (bx & 7) * 128, gy = bx >> 3;
    for (int i = tid; i < 128 * 64; i += 256) wt[i] = wcond[ob * 64 + i];
    for (int nn = 0; nn < 16; nn++) {
        int n = gy * 16 + nn;
        if (n >= NSTEP) break;
        __syncthreads();
        if (tid < 128) {
            int b = tid >> 6, c = tid & 63;
            col[tid] = g_ds2[(b * 64 + c) * 256 + n];
        }
        __syncthreads();
        int oo = tid >> 1, b = tid & 1;
        const float4* w4 = (const float4*)(wt + oo * 64);
        const float4* c4 = (const float4*)(col + b * 64);
        float acc = 0.f;
#pragma unroll
        for (int j = 0; j < 16; j++) acc += dot4(w4[j], c4[j]);
        g_cond[(n * 2 + b) * 1024 + ob + oo] = acc;
    }
}

// SMEM floats
#define S_RING 0
#define S_SC   16320
#define S_GVB  18368
#define S_SB   18880
#define S_X0   19392
#define S_HB   19456
#define S_H2   19712
#define S_YV   19968
#define S_TOT  20032

__constant__ int c_dil[8]  = {1, 2, 4, 8, 16, 32, 64, 128};
__constant__ int c_roff[8] = {0, 1, 3, 7, 15, 31, 63, 127};

__global__ void __launch_bounds__(1024, 1)
k_loop(const float* __restrict__ wembed, const float* __restrict__ wres,
       const float* __restrict__ wskip, const float* __restrict__ wout,
       const float* __restrict__ wend) {
    extern __shared__ float sm[];
    float* ring = sm + S_RING;
    float* sc   = sm + S_SC;
    float* gvb  = sm + S_GVB;
    float* sb   = sm + S_SB;     // s_0..s_7 (s_0 stays 0)
    float* x0b  = sm + S_X0;
    float* hb   = sm + S_HB;
    float* h2   = sm + S_H2;
    float* yv   = sm + S_YV;
    const int b = blockIdx.x, tid = threadIdx.x;

    for (int i = tid; i < S_TOT; i += 1024) sm[i] = 0.f;
    __syncthreads();
    sc[tid] = g_cond[b * 1024 + tid];        // cond step 0 -> buf 0
    __syncthreads();

    // A-half row mapping (tid<512)
    const int lane = tid & 31, wid = tid >> 5;
    const int qa = lane & 3, half = (lane >> 4) & 1, ridx = (lane >> 2) & 3;
    const int rowA = half * 64 + wid * 4 + ridx;      // output row in [0,128)
    const int rlo  = wid * 4 + ridx;                  // gate output row (<64)
    float skip_acc = 0.f;                             // B skip threads only

    for (int n = 0; n < NSTEP; n++) {
        const float* scur = sc + (n & 1) * 1024;
#pragma unroll
        for (int l = 0; l < 8; l++) {
            if (tid < 512) {
                // z_l = Wbig_l[row] . [old_l | y | s_{l-1} | g_{l-1}] + c_l
                const float4* Wr = (const float4*)g_Wbig
                                 + (l * 128 + rowA) * 64 + qa * 16;
                const int slot = c_roff[l] + (n & (c_dil[l] - 1));
                const float* vb = (qa == 0) ? ring + slot * 64
                               : (qa == 1) ? yv
                               : (qa == 2) ? sb + (l >= 1 ? l - 1 : 0) * 64
                                           : gvb + ((l + 7) & 7) * 64;
                const float4* v4 = (const float4*)vb;
                float a0 = 0.f, a1 = 0.f;
#pragma unroll
                for (int j = 0; j < 8; j++) {
                    a0 += dot4(Wr[2 * j], v4[2 * j]);
                    a1 += dot4(Wr[2 * j + 1], v4[2 * j + 1]);
                }
                float acc = a0 + a1;
                acc += __shfl_xor_sync(~0u, acc, 1);
                acc += __shfl_xor_sync(~0u, acc, 2);
                float z = acc + scur[l * 128 + rowA];
                float zp = __shfl_xor_sync(~0u, z, 16);
                if (half == 0 && qa == 0) gvb[l * 64 + rlo] = gatefn(z, zp);
            } else if (l == 0) {
                int t = tid - 512;
                if (t < 256) {       // x_0 = Wembed . y
                    int row = t >> 2, q = t & 3;
                    const float4* w4 = (const float4*)wembed + row * 16 + q * 4;
                    const float4* y4 = (const float4*)yv + q * 4;
                    float a = dot4(w4[0], y4[0]) + dot4(w4[1], y4[1])
                            + dot4(w4[2], y4[2]) + dot4(w4[3], y4[3]);
                    a += __shfl_xor_sync(~0u, a, 1);
                    a += __shfl_xor_sync(~0u, a, 2);
                    if (q == 0) x0b[row] = a;
                } else if (n + 1 < NSTEP) {   // cond prefetch (256 x 1 float4)
                    int t3 = t - 256;
                    const float4* gc = (const float4*)(g_cond + ((n + 1) * 2 + b) * 1024);
                    float4* sn = (float4*)(sc + ((n + 1) & 1) * 1024);
                    sn[t3] = gc[t3];
                }
            } else {
                int t = tid - 512;
                if (t < 256) {       // skip_{l-1}: full 64-dot, register acc
                    const float4* w4 = (const float4*)wskip + ((l - 1) * 256 + t) * 16;
                    const float4* g4 = (const float4*)(gvb + (l - 1) * 64);
                    float c0 = 0.f, c1 = 0.f;
#pragma unroll
                    for (int j = 0; j < 8; j++) {
                        c0 += dot4(w4[2 * j], g4[2 * j]);
                        c1 += dot4(w4[2 * j + 1], g4[2 * j + 1]);
                    }
                    skip_acc += c0 + c1;
                } else {             // s_l = s_{l-1} + Wres_{l-1} g_{l-1}
                    int t3 = t - 256, row = t3 >> 2, q = t3 & 3;
                    const float4* w4 = (const float4*)wres
                                     + ((l - 1) * 64 + row) * 16 + q * 4;
                    const float4* g4 = (const float4*)(gvb + (l - 1) * 64) + q * 4;
                    float a = dot4(w4[0], g4[0]) + dot4(w4[1], g4[1])
                            + dot4(w4[2], g4[2]) + dot4(w4[3], g4[3]);
                    a += __shfl_xor_sync(~0u, a, 1);
                    a += __shfl_xor_sync(~0u, a, 2);
                    if (q == 0) sb[l * 64 + row] = sb[(l - 1) * 64 + row] + a;
                }
            }
            __syncthreads();
        }
        // P_8: skip_7 + store hb; ring writes x_l = x0 + s_l
        if (tid < 512) {
            int l8 = tid >> 6, r8 = tid & 63;
            int slot = c_roff[l8] + (n & (c_dil[l8] - 1));
            ring[slot * 64 + r8] = x0b[r8] + sb[l8 * 64 + r8];
        } else if (tid < 768) {
            int t = tid - 512;
            const float4* w4 = (const float4*)wskip + (7 * 256 + t) * 16;
            const float4* g4 = (const float4*)(gvb + 7 * 64);
            float c0 = 0.f, c1 = 0.f;
#pragma unroll
            for (int j = 0; j < 8; j++) {
                c0 += dot4(w4[2 * j], g4[2 * j]);
                c1 += dot4(w4[2 * j + 1], g4[2 * j + 1]);
            }
            hb[t] = fmaxf(skip_acc + c0 + c1, 0.f);
            skip_acc = 0.f;
        }
        __syncthreads();
        // P_9: h2 = relu(wout . hb)
        {
            int row = tid >> 2, q = tid & 3;
            const float4* w4 = (const float4*)wout + row * 64 + q * 16;
            const float4* v4 = (const float4*)hb + q * 16;
            float c0 = 0.f, c1 = 0.f;
#pragma unroll
            for (int j = 0; j < 8; j++) {
                c0 += dot4(w4[2 * j], v4[2 * j]);
                c1 += dot4(w4[2 * j + 1], v4[2 * j + 1]);
            }
            float acc = c0 + c1;
            acc += __shfl_xor_sync(~0u, acc, 1);
            acc += __shfl_xor_sync(~0u, acc, 2);
            if (q == 0) h2[row] = fmaxf(acc, 0.f);
        }
        __syncthreads();
        // P_10: y = wend . h2
        {
            int row = tid >> 4, q = tid & 15;
            const float4* w4 = (const float4*)wend + row * 64 + q * 4;
            const float4* h4 = (const float4*)h2 + q * 4;
            float acc = dot4(w4[0], h4[0]) + dot4(w4[1], h4[1])
                      + dot4(w4[2], h4[2]) + dot4(w4[3], h4[3]);
            acc += __shfl_xor_sync(~0u, acc, 1);
            acc += __shfl_xor_sync(~0u, acc, 2);
            acc += __shfl_xor_sync(~0u, acc, 4);
            acc += __shfl_xor_sync(~0u, acc, 8);
            if (q == 0) {
                yv[row] = acc;
                g_outpre[(b * 64 + row) * 256 + n + 1] = acc;
            }
        }
        __syncthreads();
    }
}

extern "C" void kernel_launch(void* const* d_in, const int* in_sizes, int n_in,
                              void* d_out, int out_size) {
    const float* song   = (const float*)d_in[0];
    const float* ds_w   = (const float*)d_in[1];
    const float* ds_g   = (const float*)d_in[2];
    const float* ds_b   = (const float*)d_in[3];
    const float* us_w   = (const float*)d_in[4];
    const float* us_g   = (const float*)d_in[5];
    const float* us_b   = (const float*)d_in[6];
    const float* wembed = (const float*)d_in[7];
    const float* wcond  = (const float*)d_in[8];
    const float* wdil   = (const float*)d_in[9];
    const float* wres   = (const float*)d_in[10];
    const float* wskip  = (const float*)d_in[11];
    const float* wout   = (const float*)d_in[12];
    const float* wend   = (const float*)d_in[13];
    float* out = (float*)d_out;

    cudaFuncSetAttribute(k_loop, cudaFuncAttributeMaxDynamicSharedMemorySize,
                         S_TOT * 4);
    k_downbn<<<64, 256>>>(0, ds_w, song, ds_g, ds_b);
    k_downbn<<<64, 256>>>(1, ds_w + 8192, song, ds_g + 64, ds_b + 64);
    k_prep<<<1153, 256>>>(wdil, wcond, wres, wembed);
    k_loop<<<2, 1024, S_TOT * 4>>>(wembed, wres, wskip, wout, wend);
    k_upbn<<<64, 256>>>(0, us_w, us_g, us_b, nullptr);
    k_upbn<<<64, 256>>>(1, us_w + 8192, us_g + 64, us_b + 64, out);
}